// round 16
// baseline (speedup 1.0000x reference)
#include <cuda_runtime.h>
#include <cstdint>

#define N_NODES 64
#define N_EDGES 512
#define N_ACT   16
#define ITERS   8
#define N_BATCH 512
#define MSG_STRIDE 17   // padded row stride for mf/mb (minimal cross-half-warp bank overlap)

static constexpr float INV_E = 1.0f / 512.0f;
static constexpr float INV_N = 1.0f / 64.0f;
static constexpr float INV_A = 1.0f / 16.0f;

// 4x4 register transpose among 4 lanes at xor-distances d0 (rank bit0), d1 (rank bit1).
__device__ __forceinline__ void xpose4(float& p0, float& p1, float& p2, float& p3,
                                       int m, int d0, int d1) {
    float t;
    t = __shfl_xor_sync(0xffffffffu, (m & 1) ? p0 : p1, d0);
    if (m & 1) p0 = t; else p1 = t;
    t = __shfl_xor_sync(0xffffffffu, (m & 1) ? p2 : p3, d0);
    if (m & 1) p2 = t; else p3 = t;
    t = __shfl_xor_sync(0xffffffffu, (m & 2) ? p0 : p2, d1);
    if (m & 2) p0 = t; else p2 = t;
    t = __shfl_xor_sync(0xffffffffu, (m & 2) ? p1 : p3, d1);
    if (m & 2) p1 = t; else p3 = t;
}

// -------- adjacency (batch-independent), built deterministically per launch --------
__device__ int g_in_start[N_NODES + 1];
__device__ int g_out_start[N_NODES + 1];
__device__ int g_in_list[N_EDGES];
__device__ int g_out_list[N_EDGES];

__global__ void DCG_prep_kernel(const int* __restrict__ ef_g, const int* __restrict__ et_g) {
    __shared__ int sf[N_EDGES], st[N_EDGES];
    __shared__ int cin[N_NODES], cout[N_NODES];
    int tid = threadIdx.x;
    for (int e = tid; e < N_EDGES; e += blockDim.x) { sf[e] = ef_g[e]; st[e] = et_g[e]; }
    __syncthreads();
    if (tid < N_NODES) {
        int n = tid, c = 0;
        for (int e = 0; e < N_EDGES; e++) if (st[e] == n) c++;
        cin[n] = c;
    } else if (tid < 2 * N_NODES) {
        int n = tid - N_NODES, c = 0;
        for (int e = 0; e < N_EDGES; e++) if (sf[e] == n) c++;
        cout[n] = c;
    }
    __syncthreads();
    if (tid == 0) {
        int s = 0;
        for (int n = 0; n < N_NODES; n++) { g_in_start[n] = s; s += cin[n]; }
        g_in_start[N_NODES] = s;
    } else if (tid == 1) {
        int s = 0;
        for (int n = 0; n < N_NODES; n++) { g_out_start[n] = s; s += cout[n]; }
        g_out_start[N_NODES] = s;
    }
    __syncthreads();
    if (tid < N_NODES) {
        int n = tid, p = g_in_start[n];
        for (int e = 0; e < N_EDGES; e++) if (st[e] == n) g_in_list[p++] = e;
    } else if (tid < 2 * N_NODES) {
        int n = tid - N_NODES, p = g_out_start[n];
        for (int e = 0; e < N_EDGES; e++) if (sf[e] == n) g_out_list[p++] = e;
    }
}

// -------- shared memory layout --------
static constexpr int OFF_Q0  = 0;
static constexpr int OFF_Q   = 1024;
static constexpr int OFF_NVS = 2048;
static constexpr int OFF_MF  = 3072;                    // 512*17 = 8704
static constexpr int OFF_MB  = 11792;                   // 512*17 = 8704 (+16 pad)
static constexpr int OFF_EVS = 20496;                   // 9*512  = 4608
static constexpr int OFF_QV  = 25104;                   // 16
static constexpr int OFF_AUX = 25120;                   // 2
static constexpr int SMEM_FLOATS = 25122;
static constexpr int SMEM_INTS   = 2755;
static constexpr int SMEM_BYTES  = (SMEM_FLOATS + SMEM_INTS) * 4;   // 111,508 B -> 1 CTA/SM

__global__ __launch_bounds__(1024, 1)
void DCG_main_kernel(const float* __restrict__ node_vals,
                     const float* __restrict__ edge_vals,
                     const int* __restrict__ ef_g,
                     const int* __restrict__ et_g,
                     float* __restrict__ out) {
    extern __shared__ float sm[];
    float* q0   = sm + OFF_Q0;
    float* q    = sm + OFF_Q;
    float* nvs  = sm + OFF_NVS;
    float* mf   = sm + OFF_MF;
    float* mb   = sm + OFF_MB;
    float* evs  = sm + OFF_EVS;
    float* qv   = sm + OFF_QV;
    int* si     = (int*)(sm + SMEM_FLOATS);
    int* ef     = si;
    int* et     = si + 512;
    int* ins    = si + 1024;
    int* outs   = si + 1089;
    int* inl    = si + 1154;
    int* outl   = si + 1666;
    int* a_hist = si + 2178;      // 9 * 64
    int* s_bc   = si + 2754;

    const int tid  = threadIdx.x;
    const int b    = blockIdx.x;
    const int warp = tid >> 5;
    const int lane = tid & 31;
    const int h    = lane & 15;        // id within half-warp
    const int hw   = lane >> 4;        // which edge of the pair
    const int r0   = h >> 2;           // base row (rows r0, r0+4, r0+8, r0+12)
    const int c4   = (h & 3) << 2;     // base col (cols c4..c4+3)
    const int base16 = lane & 16;
    const int perm = c4 + r0;          // 4*(h&3) + (h>>2): output index this lane stores

    // ---- load static data ----
    for (int i = tid; i < N_EDGES; i += 1024) {
        ef[i]   = ef_g[i];
        et[i]   = et_g[i];
        inl[i]  = g_in_list[i];
        outl[i] = g_out_list[i];
    }
    if (tid < N_NODES + 1) { ins[tid] = g_in_start[tid]; outs[tid] = g_out_start[tid]; }

    const float* nv = node_vals + (size_t)b * (N_NODES * N_ACT);
    {
        float raw = nv[tid];
        nvs[tid] = raw;
        float v = raw * INV_N;    // exact (power of two)
        q0[tid] = v;
        q[tid]  = v;
    }
    for (int i = tid; i < N_EDGES * MSG_STRIDE; i += 1024) { mf[i] = 0.0f; mb[i] = 0.0f; }
    __syncthreads();

    // ---- candidate 0: argmax(node_vals) ----
    if (tid < N_NODES) {
        const float* row = nvs + tid * N_ACT;
        int best = 0; float bv = row[0];
        #pragma unroll
        for (int a = 1; a < N_ACT; a++) { float v = row[a]; if (v > bv) { bv = v; best = a; } }
        a_hist[tid] = best;
    }
    __syncthreads();

    const float* ebase = edge_vals + (size_t)b * (N_EDGES * N_ACT * N_ACT);

    // normalization row assignment: lane L owns edge (L&7)*64 + warp*2 + ((L>>3)&1),
    // direction mf for lanes 0-15, mb for lanes 16-31. rot spreads banks.
    const int nk   = lane & 7;
    const int nhw  = (lane >> 3) & 1;
    const int ne   = nk * 64 + warp * 2 + nhw;
    float* nrow    = ((lane >> 4) ? mb : mf) + ne * MSG_STRIDE;
    const int nrot = (nk * 2) & 15;

    // ================= message-passing iterations =================
    for (int it = 0; it < ITERS; it++) {
        // ---- phase 0 (overlapped): warps 30-31 record argmax of q from the PREVIOUS
        // iteration (it >= 1). Safe concurrency: phase 1 only reads q, only writes mf/mb
        // rows it exclusively owns; this block only reads q and writes a_hist.
        if (it > 0 && tid >= 960) {
            const int n = tid - 960;   // 0..63
            const float* row = q + n * N_ACT;
            int best = 0; float bv = row[0];
            #pragma unroll
            for (int a = 1; a < N_ACT; a++) { float v = row[a]; if (v > bv) { bv = v; best = a; } }
            a_hist[it * N_NODES + n] = best;
        }

        // ---- phase 1: half-warp per edge, register-resident tiles, transpose-reduce,
        //      software-pipelined c/index loads ----
        {
            int e_n  = warp * 2 + hw;             // k = 0 edge
            int fn_n = ef[e_n], tn_n = et[e_n];
            float c1_n = q[fn_n * N_ACT + h] - mb[e_n * MSG_STRIDE + h];
            float c2_n = q[tn_n * N_ACT + h] - mf[e_n * MSG_STRIDE + h];

            #pragma unroll
            for (int k = 0; k < 8; k++) {
                const int e = e_n;
                const float c1 = c1_n;
                const float c2 = c2_n;

                // tile -> registers (issue LDGs first)
                const float4* src4 = (const float4*)(ebase + (size_t)e * 256);
                float4 v0 = src4[h];
                float4 v1 = src4[h + 16];
                float4 v2 = src4[h + 32];
                float4 v3 = src4[h + 48];

                // prefetch next k's indices and c values (edge exclusively owned by this
                // half-warp; its mf/mb row unwritten until that k's store -> hazard-free)
                if (k < 7) {
                    e_n  = (k + 1) * 64 + warp * 2 + hw;
                    fn_n = ef[e_n]; tn_n = et[e_n];
                    c1_n = q[fn_n * N_ACT + h] - mb[e_n * MSG_STRIDE + h];
                    c2_n = q[tn_n * N_ACT + h] - mf[e_n * MSG_STRIDE + h];
                }

                // distribute c (8 shuffles, both edges of the warp at once)
                float cf0 = __shfl_sync(0xffffffffu, c1, base16 | r0);
                float cf1 = __shfl_sync(0xffffffffu, c1, base16 | (r0 + 4));
                float cf2 = __shfl_sync(0xffffffffu, c1, base16 | (r0 + 8));
                float cf3 = __shfl_sync(0xffffffffu, c1, base16 | (r0 + 12));
                float ct0 = __shfl_sync(0xffffffffu, c2, base16 | c4);
                float ct1 = __shfl_sync(0xffffffffu, c2, base16 | (c4 + 1));
                float ct2 = __shfl_sync(0xffffffffu, c2, base16 | (c4 + 2));
                float ct3 = __shfl_sync(0xffffffffu, c2, base16 | (c4 + 3));

                // forward (column max) partials over the 4 in-register rows
                float pf0 = fmaxf(fmaxf(fmaf(v0.x, INV_E, cf0), fmaf(v1.x, INV_E, cf1)),
                                  fmaxf(fmaf(v2.x, INV_E, cf2), fmaf(v3.x, INV_E, cf3)));
                float pf1 = fmaxf(fmaxf(fmaf(v0.y, INV_E, cf0), fmaf(v1.y, INV_E, cf1)),
                                  fmaxf(fmaf(v2.y, INV_E, cf2), fmaf(v3.y, INV_E, cf3)));
                float pf2 = fmaxf(fmaxf(fmaf(v0.z, INV_E, cf0), fmaf(v1.z, INV_E, cf1)),
                                  fmaxf(fmaf(v2.z, INV_E, cf2), fmaf(v3.z, INV_E, cf3)));
                float pf3 = fmaxf(fmaxf(fmaf(v0.w, INV_E, cf0), fmaf(v1.w, INV_E, cf1)),
                                  fmaxf(fmaf(v2.w, INV_E, cf2), fmaf(v3.w, INV_E, cf3)));

                // backward (row max) partials over the 4 in-register cols
                float pb0 = fmaxf(fmaxf(fmaf(v0.x, INV_E, ct0), fmaf(v0.y, INV_E, ct1)),
                                  fmaxf(fmaf(v0.z, INV_E, ct2), fmaf(v0.w, INV_E, ct3)));
                float pb1 = fmaxf(fmaxf(fmaf(v1.x, INV_E, ct0), fmaf(v1.y, INV_E, ct1)),
                                  fmaxf(fmaf(v1.z, INV_E, ct2), fmaf(v1.w, INV_E, ct3)));
                float pb2 = fmaxf(fmaxf(fmaf(v2.x, INV_E, ct0), fmaf(v2.y, INV_E, ct1)),
                                  fmaxf(fmaf(v2.z, INV_E, ct2), fmaf(v2.w, INV_E, ct3)));
                float pb3 = fmaxf(fmaxf(fmaf(v3.x, INV_E, ct0), fmaf(v3.y, INV_E, ct1)),
                                  fmaxf(fmaf(v3.z, INV_E, ct2), fmaf(v3.w, INV_E, ct3)));

                // transpose-reduce
                xpose4(pf0, pf1, pf2, pf3, r0, 4, 8);
                float rf = fmaxf(fmaxf(pf0, pf1), fmaxf(pf2, pf3));
                xpose4(pb0, pb1, pb2, pb3, h & 3, 1, 2);
                float rb = fmaxf(fmaxf(pb0, pb1), fmaxf(pb2, pb3));

                // lane h stores output index perm for both directions
                mf[e * MSG_STRIDE + perm] = rf;
                mb[e * MSG_STRIDE + perm] = rb;
            }
        }

        // ---- phase 1b (warp-local, no block barrier): normalize this warp's 32 rows ----
        // All 32 rows (16 edges x {mf,mb}) were written exclusively by this warp.
        __syncwarp();
        {
            float v[16];
            #pragma unroll
            for (int j = 0; j < 16; j++) {          // rotated visit order for banking;
                int i = (j + nrot) & 15;            // register slots hold true index
                v[i] = nrow[i];
            }
            float s = v[0];
            #pragma unroll
            for (int i = 1; i < 16; i++) s += v[i]; // STRICT in-order sum
            float mean = s * INV_A;
            #pragma unroll
            for (int j = 0; j < 16; j++) {
                int i = (j + nrot) & 15;
                nrow[i] = v[i] - mean;
            }
        }
        __syncthreads();

        // ---- phase 2: q = q0 + scatter(mf by to) + scatter(mb by from), ascending edge order ----
        {
            int n = tid >> 4, a = tid & 15;
            float acc = q0[tid];
            int s0 = ins[n], s1 = ins[n + 1];
            for (int kk = s0; kk < s1; kk++) acc += mf[inl[kk] * MSG_STRIDE + a];
            s0 = outs[n]; s1 = outs[n + 1];
            for (int kk = s0; kk < s1; kk++) acc += mb[outl[kk] * MSG_STRIDE + a];
            q[tid] = acc;
        }
        __syncthreads();
        // (no phase-3 barrier: argmax of this q happens concurrently with next phase 1)
    }

    // ---- final candidate argmax (q from last iteration) ----
    if (tid < N_NODES) {
        const float* row = q + tid * N_ACT;
        int best = 0; float bv = row[0];
        #pragma unroll
        for (int a = 1; a < N_ACT; a++) { float v = row[a]; if (v > bv) { bv = v; best = a; } }
        a_hist[ITERS * N_NODES + tid] = best;
    }
    __syncthreads();

    // ================= deferred evals: 9 candidates in parallel =================
    for (int idx = tid; idx < 9 * N_EDGES; idx += 1024) {
        int c = idx >> 9, e = idx & 511;
        int af = a_hist[c * N_NODES + ef[e]];
        int at = a_hist[c * N_NODES + et[e]];
        evs[idx] = ebase[(size_t)e * 256 + af * 16 + at];
    }
    __syncthreads();
    // strict in-order sums, one lane per candidate (XLA-CPU sequential order)
    if (tid < 9) {
        const float* ev = evs + tid * N_EDGES;
        float es = 0.0f;
        #pragma unroll 8
        for (int e = 0; e < N_EDGES; e++) es += ev[e];
        const int* ah = a_hist + tid * N_NODES;
        float ns = 0.0f;
        #pragma unroll 8
        for (int n = 0; n < N_NODES; n++) ns += nvs[n * N_ACT + ah[n]];
        qv[tid] = ns * INV_N + es * INV_E;
    }
    __syncthreads();
    if (tid == 0) {
        float qm = qv[0]; int bc = 0;
        #pragma unroll
        for (int i = 1; i < 9; i++) { if (qv[i] > qm) { qm = qv[i]; bc = i; } }
        sm[OFF_AUX] = qm;
        *s_bc = bc;
    }
    __syncthreads();

    // ---- output: q_max[512] then a_max[512*64] (as float) ----
    if (tid == 0) out[b] = sm[OFF_AUX];
    if (tid < N_NODES) out[N_BATCH + b * N_NODES + tid] = (float)a_hist[(*s_bc) * N_NODES + tid];
}

extern "C" void kernel_launch(void* const* d_in, const int* in_sizes, int n_in,
                              void* d_out, int out_size) {
    const float* node_vals = (const float*)d_in[0];
    const float* edge_vals = (const float*)d_in[1];
    const int*   ef        = (const int*)d_in[2];
    const int*   et        = (const int*)d_in[3];
    float*       out       = (float*)d_out;

    static bool attr_set = false;
    if (!attr_set) {
        cudaFuncSetAttribute(DCG_main_kernel,
                             cudaFuncAttributeMaxDynamicSharedMemorySize, SMEM_BYTES);
        attr_set = true;
    }

    DCG_prep_kernel<<<1, 128>>>(ef, et);
    DCG_main_kernel<<<N_BATCH, 1024, SMEM_BYTES>>>(node_vals, edge_vals, ef, et, out);
}

// round 17
// speedup vs baseline: 1.4229x; 1.4229x over previous
#include <cuda_runtime.h>
#include <cstdint>

#define N_NODES 64
#define N_EDGES 512
#define N_ACT   16
#define ITERS   8
#define N_BATCH 512
#define MSG_STRIDE 17   // padded row stride for mf/mb (minimal cross-half-warp bank overlap)

static constexpr float INV_E = 1.0f / 512.0f;
static constexpr float INV_N = 1.0f / 64.0f;
static constexpr float INV_A = 1.0f / 16.0f;

// 4x4 register transpose among 4 lanes at xor-distances d0 (rank bit0), d1 (rank bit1).
__device__ __forceinline__ void xpose4(float& p0, float& p1, float& p2, float& p3,
                                       int m, int d0, int d1) {
    float t;
    t = __shfl_xor_sync(0xffffffffu, (m & 1) ? p0 : p1, d0);
    if (m & 1) p0 = t; else p1 = t;
    t = __shfl_xor_sync(0xffffffffu, (m & 1) ? p2 : p3, d0);
    if (m & 1) p2 = t; else p3 = t;
    t = __shfl_xor_sync(0xffffffffu, (m & 2) ? p0 : p2, d1);
    if (m & 2) p0 = t; else p2 = t;
    t = __shfl_xor_sync(0xffffffffu, (m & 2) ? p1 : p3, d1);
    if (m & 2) p1 = t; else p3 = t;
}

// -------- adjacency (batch-independent), built deterministically per launch --------
__device__ int g_in_start[N_NODES + 1];
__device__ int g_out_start[N_NODES + 1];
__device__ int g_in_list[N_EDGES];
__device__ int g_out_list[N_EDGES];

__global__ void DCG_prep_kernel(const int* __restrict__ ef_g, const int* __restrict__ et_g) {
    __shared__ int sf[N_EDGES], st[N_EDGES];
    __shared__ int cin[N_NODES], cout[N_NODES];
    int tid = threadIdx.x;
    for (int e = tid; e < N_EDGES; e += blockDim.x) { sf[e] = ef_g[e]; st[e] = et_g[e]; }
    __syncthreads();
    if (tid < N_NODES) {
        int n = tid, c = 0;
        for (int e = 0; e < N_EDGES; e++) if (st[e] == n) c++;
        cin[n] = c;
    } else if (tid < 2 * N_NODES) {
        int n = tid - N_NODES, c = 0;
        for (int e = 0; e < N_EDGES; e++) if (sf[e] == n) c++;
        cout[n] = c;
    }
    __syncthreads();
    if (tid == 0) {
        int s = 0;
        for (int n = 0; n < N_NODES; n++) { g_in_start[n] = s; s += cin[n]; }
        g_in_start[N_NODES] = s;
    } else if (tid == 1) {
        int s = 0;
        for (int n = 0; n < N_NODES; n++) { g_out_start[n] = s; s += cout[n]; }
        g_out_start[N_NODES] = s;
    }
    __syncthreads();
    if (tid < N_NODES) {
        int n = tid, p = g_in_start[n];
        for (int e = 0; e < N_EDGES; e++) if (st[e] == n) g_in_list[p++] = e;
    } else if (tid < 2 * N_NODES) {
        int n = tid - N_NODES, p = g_out_start[n];
        for (int e = 0; e < N_EDGES; e++) if (sf[e] == n) g_out_list[p++] = e;
    }
}

// -------- shared memory layout --------
static constexpr int OFF_Q0  = 0;
static constexpr int OFF_Q   = 1024;
static constexpr int OFF_NVS = 2048;
static constexpr int OFF_MF  = 3072;                    // 512*17 = 8704
static constexpr int OFF_MB  = 11792;                   // 512*17 = 8704 (+16 pad)
static constexpr int OFF_EVS = 20496;                   // 9*512  = 4608
static constexpr int OFF_QV  = 25104;                   // 16
static constexpr int OFF_AUX = 25120;                   // 2
static constexpr int SMEM_FLOATS = 25122;
static constexpr int SMEM_INTS   = 2755;
static constexpr int SMEM_BYTES  = (SMEM_FLOATS + SMEM_INTS) * 4;   // 111,508 B -> 1 CTA/SM

__global__ __launch_bounds__(1024, 1)
void DCG_main_kernel(const float* __restrict__ node_vals,
                     const float* __restrict__ edge_vals,
                     const int* __restrict__ ef_g,
                     const int* __restrict__ et_g,
                     float* __restrict__ out) {
    extern __shared__ float sm[];
    float* q0   = sm + OFF_Q0;
    float* q    = sm + OFF_Q;
    float* nvs  = sm + OFF_NVS;
    float* mf   = sm + OFF_MF;
    float* mb   = sm + OFF_MB;
    float* evs  = sm + OFF_EVS;
    float* qv   = sm + OFF_QV;
    int* si     = (int*)(sm + SMEM_FLOATS);
    int* ef     = si;
    int* et     = si + 512;
    int* ins    = si + 1024;
    int* outs   = si + 1089;
    int* inl    = si + 1154;
    int* outl   = si + 1666;
    int* a_hist = si + 2178;      // 9 * 64
    int* s_bc   = si + 2754;

    const int tid  = threadIdx.x;
    const int b    = blockIdx.x;
    const int warp = tid >> 5;
    const int lane = tid & 31;
    const int h    = lane & 15;        // id within half-warp
    const int hw   = lane >> 4;        // which edge of the pair
    const int r0   = h >> 2;           // base row (rows r0, r0+4, r0+8, r0+12)
    const int c4   = (h & 3) << 2;     // base col (cols c4..c4+3)
    const int base16 = lane & 16;
    const int perm = c4 + r0;          // 4*(h&3) + (h>>2): output index this lane stores

    // ---- load static data ----
    for (int i = tid; i < N_EDGES; i += 1024) {
        ef[i]   = ef_g[i];
        et[i]   = et_g[i];
        inl[i]  = g_in_list[i];
        outl[i] = g_out_list[i];
    }
    if (tid < N_NODES + 1) { ins[tid] = g_in_start[tid]; outs[tid] = g_out_start[tid]; }

    const float* nv = node_vals + (size_t)b * (N_NODES * N_ACT);
    {
        float raw = nv[tid];
        nvs[tid] = raw;
        float v = raw * INV_N;    // exact (power of two)
        q0[tid] = v;
        q[tid]  = v;
    }
    for (int i = tid; i < N_EDGES * MSG_STRIDE; i += 1024) { mf[i] = 0.0f; mb[i] = 0.0f; }
    __syncthreads();

    // ---- candidate 0: argmax(node_vals) ----
    if (tid < N_NODES) {
        const float* row = nvs + tid * N_ACT;
        int best = 0; float bv = row[0];
        #pragma unroll
        for (int a = 1; a < N_ACT; a++) { float v = row[a]; if (v > bv) { bv = v; best = a; } }
        a_hist[tid] = best;
    }
    __syncthreads();

    const float* ebase = edge_vals + (size_t)b * (N_EDGES * N_ACT * N_ACT);

    // ================= message-passing iterations =================
    for (int it = 0; it < ITERS; it++) {
        // ---- phase 0 (overlapped): warps 30-31 record argmax of q from the PREVIOUS
        // iteration (it >= 1). Safe concurrency: phase 1 only reads q, only writes mf/mb
        // rows it exclusively owns; this block only reads q and writes a_hist.
        if (it > 0 && tid >= 960) {
            const int n = tid - 960;   // 0..63
            const float* row = q + n * N_ACT;
            int best = 0; float bv = row[0];
            #pragma unroll
            for (int a = 1; a < N_ACT; a++) { float v = row[a]; if (v > bv) { bv = v; best = a; } }
            a_hist[it * N_NODES + n] = best;
        }

        // ---- phase 1: half-warp per edge, register-resident tiles, transpose-reduce,
        //      software-pipelined c/index loads ----
        {
            int e_n  = warp * 2 + hw;             // k = 0 edge
            int fn_n = ef[e_n], tn_n = et[e_n];
            float c1_n = q[fn_n * N_ACT + h] - mb[e_n * MSG_STRIDE + h];
            float c2_n = q[tn_n * N_ACT + h] - mf[e_n * MSG_STRIDE + h];

            #pragma unroll
            for (int k = 0; k < 8; k++) {
                const int e = e_n;
                const float c1 = c1_n;
                const float c2 = c2_n;

                // tile -> registers (issue LDGs first)
                const float4* src4 = (const float4*)(ebase + (size_t)e * 256);
                float4 v0 = src4[h];
                float4 v1 = src4[h + 16];
                float4 v2 = src4[h + 32];
                float4 v3 = src4[h + 48];

                // prefetch next k's indices and c values (edge exclusively owned by this
                // half-warp; its mf/mb row unwritten until that k's store -> hazard-free)
                if (k < 7) {
                    e_n  = (k + 1) * 64 + warp * 2 + hw;
                    fn_n = ef[e_n]; tn_n = et[e_n];
                    c1_n = q[fn_n * N_ACT + h] - mb[e_n * MSG_STRIDE + h];
                    c2_n = q[tn_n * N_ACT + h] - mf[e_n * MSG_STRIDE + h];
                }

                // distribute c (8 shuffles, both edges of the warp at once)
                float cf0 = __shfl_sync(0xffffffffu, c1, base16 | r0);
                float cf1 = __shfl_sync(0xffffffffu, c1, base16 | (r0 + 4));
                float cf2 = __shfl_sync(0xffffffffu, c1, base16 | (r0 + 8));
                float cf3 = __shfl_sync(0xffffffffu, c1, base16 | (r0 + 12));
                float ct0 = __shfl_sync(0xffffffffu, c2, base16 | c4);
                float ct1 = __shfl_sync(0xffffffffu, c2, base16 | (c4 + 1));
                float ct2 = __shfl_sync(0xffffffffu, c2, base16 | (c4 + 2));
                float ct3 = __shfl_sync(0xffffffffu, c2, base16 | (c4 + 3));

                // forward (column max) partials over the 4 in-register rows
                float pf0 = fmaxf(fmaxf(fmaf(v0.x, INV_E, cf0), fmaf(v1.x, INV_E, cf1)),
                                  fmaxf(fmaf(v2.x, INV_E, cf2), fmaf(v3.x, INV_E, cf3)));
                float pf1 = fmaxf(fmaxf(fmaf(v0.y, INV_E, cf0), fmaf(v1.y, INV_E, cf1)),
                                  fmaxf(fmaf(v2.y, INV_E, cf2), fmaf(v3.y, INV_E, cf3)));
                float pf2 = fmaxf(fmaxf(fmaf(v0.z, INV_E, cf0), fmaf(v1.z, INV_E, cf1)),
                                  fmaxf(fmaf(v2.z, INV_E, cf2), fmaf(v3.z, INV_E, cf3)));
                float pf3 = fmaxf(fmaxf(fmaf(v0.w, INV_E, cf0), fmaf(v1.w, INV_E, cf1)),
                                  fmaxf(fmaf(v2.w, INV_E, cf2), fmaf(v3.w, INV_E, cf3)));

                // backward (row max) partials over the 4 in-register cols
                float pb0 = fmaxf(fmaxf(fmaf(v0.x, INV_E, ct0), fmaf(v0.y, INV_E, ct1)),
                                  fmaxf(fmaf(v0.z, INV_E, ct2), fmaf(v0.w, INV_E, ct3)));
                float pb1 = fmaxf(fmaxf(fmaf(v1.x, INV_E, ct0), fmaf(v1.y, INV_E, ct1)),
                                  fmaxf(fmaf(v1.z, INV_E, ct2), fmaf(v1.w, INV_E, ct3)));
                float pb2 = fmaxf(fmaxf(fmaf(v2.x, INV_E, ct0), fmaf(v2.y, INV_E, ct1)),
                                  fmaxf(fmaf(v2.z, INV_E, ct2), fmaf(v2.w, INV_E, ct3)));
                float pb3 = fmaxf(fmaxf(fmaf(v3.x, INV_E, ct0), fmaf(v3.y, INV_E, ct1)),
                                  fmaxf(fmaf(v3.z, INV_E, ct2), fmaf(v3.w, INV_E, ct3)));

                // transpose-reduce
                xpose4(pf0, pf1, pf2, pf3, r0, 4, 8);
                float rf = fmaxf(fmaxf(pf0, pf1), fmaxf(pf2, pf3));
                xpose4(pb0, pb1, pb2, pb3, h & 3, 1, 2);
                float rb = fmaxf(fmaxf(pb0, pb1), fmaxf(pb2, pb3));

                // lane h stores output index perm for both directions
                mf[e * MSG_STRIDE + perm] = rf;
                mb[e * MSG_STRIDE + perm] = rb;
            }
        }
        __syncthreads();

        // ---- phase 1b: subtract per-message mean (STRICT in-order sum) ----
        {
            int e  = tid >> 1;
            float* row = ((tid & 1) ? mb : mf) + e * MSG_STRIDE;
            float v[16];
            #pragma unroll
            for (int i = 0; i < 16; i++) v[i] = row[i];
            float s = v[0];
            #pragma unroll
            for (int i = 1; i < 16; i++) s += v[i];
            float mean = s * INV_A;
            #pragma unroll
            for (int i = 0; i < 16; i++) row[i] = v[i] - mean;
        }
        __syncthreads();

        // ---- phase 2: q = q0 + scatter(mf by to) + scatter(mb by from), ascending edge order ----
        {
            int n = tid >> 4, a = tid & 15;
            float acc = q0[tid];
            int s0 = ins[n], s1 = ins[n + 1];
            for (int kk = s0; kk < s1; kk++) acc += mf[inl[kk] * MSG_STRIDE + a];
            s0 = outs[n]; s1 = outs[n + 1];
            for (int kk = s0; kk < s1; kk++) acc += mb[outl[kk] * MSG_STRIDE + a];
            q[tid] = acc;
        }
        __syncthreads();
        // (no phase-3 barrier: argmax of this q happens concurrently with next phase 1)
    }

    // ---- final candidate argmax (q from last iteration) ----
    if (tid < N_NODES) {
        const float* row = q + tid * N_ACT;
        int best = 0; float bv = row[0];
        #pragma unroll
        for (int a = 1; a < N_ACT; a++) { float v = row[a]; if (v > bv) { bv = v; best = a; } }
        a_hist[ITERS * N_NODES + tid] = best;
    }
    __syncthreads();

    // ================= deferred evals: 9 candidates in parallel =================
    for (int idx = tid; idx < 9 * N_EDGES; idx += 1024) {
        int c = idx >> 9, e = idx & 511;
        int af = a_hist[c * N_NODES + ef[e]];
        int at = a_hist[c * N_NODES + et[e]];
        evs[idx] = ebase[(size_t)e * 256 + af * 16 + at];
    }
    __syncthreads();
    // strict in-order sums, one lane per candidate (XLA-CPU sequential order)
    if (tid < 9) {
        const float* ev = evs + tid * N_EDGES;
        float es = 0.0f;
        #pragma unroll 8
        for (int e = 0; e < N_EDGES; e++) es += ev[e];
        const int* ah = a_hist + tid * N_NODES;
        float ns = 0.0f;
        #pragma unroll 8
        for (int n = 0; n < N_NODES; n++) ns += nvs[n * N_ACT + ah[n]];
        qv[tid] = ns * INV_N + es * INV_E;
    }
    __syncthreads();
    if (tid == 0) {
        float qm = qv[0]; int bc = 0;
        #pragma unroll
        for (int i = 1; i < 9; i++) { if (qv[i] > qm) { qm = qv[i]; bc = i; } }
        sm[OFF_AUX] = qm;
        *s_bc = bc;
    }
    __syncthreads();

    // ---- output: q_max[512] then a_max[512*64] (as float) ----
    if (tid == 0) out[b] = sm[OFF_AUX];
    if (tid < N_NODES) out[N_BATCH + b * N_NODES + tid] = (float)a_hist[(*s_bc) * N_NODES + tid];
}

extern "C" void kernel_launch(void* const* d_in, const int* in_sizes, int n_in,
                              void* d_out, int out_size) {
    const float* node_vals = (const float*)d_in[0];
    const float* edge_vals = (const float*)d_in[1];
    const int*   ef        = (const int*)d_in[2];
    const int*   et        = (const int*)d_in[3];
    float*       out       = (float*)d_out;

    static bool attr_set = false;
    if (!attr_set) {
        cudaFuncSetAttribute(DCG_main_kernel,
                             cudaFuncAttributeMaxDynamicSharedMemorySize, SMEM_BYTES);
        attr_set = true;
    }

    DCG_prep_kernel<<<1, 128>>>(ef, et);
    DCG_main_kernel<<<N_BATCH, 1024, SMEM_BYTES>>>(node_vals, edge_vals, ef, et, out);
}